// round 12
// baseline (speedup 1.0000x reference)
#include <cuda_runtime.h>
#include <math.h>

#define BB 32
#define TT 50
#define SS 2048
#define CC 8
#define FF 32
#define SH 1024
#define SH_PAD 1056     // SH + 32 zero pad rows (halo reads reach 1032)
#define NG 128          // 4*F gates
#define RDIM 80         // 16 (x patch) + 64 (h patch)
#define POSB 256        // owned output positions per block
#define TS 9            // max fused timesteps per launch (wedge 256+8 = 264 = SLOTS)
#define NWARPS 22
#define NP 12           // slots per warp
#define SLOTS (NWARPS*NP)   // 264 computed slots
#define NTHREADS 704
#define HROWS 265       // smem h rows (reads reach row 264)
#define XTOT (BB*TT*SS*CC)

typedef unsigned long long ull;

// Persistent device state (zeroed every kernel_launch call; pad rows stay 0)
__device__ float g_h[BB][SH_PAD][FF];
__device__ float g_c[BB][SH_PAD][FF];
__device__ float4 g_w4[RDIM][FF];          // [r][f] -> (gate0, gate1, gate2, gate3)

__device__ __forceinline__ float hsig(float x) {
    return __saturatef(fmaf(x, 0.2f, 0.5f));
}

// fast tanh: 1 - 2/(exp(2x)+1); abs err ~1e-6, exact saturation
__device__ __forceinline__ float ftanh(float x) {
    float e = __expf(2.0f * x);
    return 1.0f - __fdividef(2.0f, e + 1.0f);
}

// packed f32x2 helpers
__device__ __forceinline__ ull fma2(ull a, ull b, ull c) {
    ull d;
    asm("fma.rn.f32x2 %0, %1, %2, %3;" : "=l"(d) : "l"(a), "l"(b), "l"(c));
    return d;
}
__device__ __forceinline__ ull dup2(float v) {
    ull d;
    asm("mov.b64 %0, {%1, %1};" : "=l"(d) : "f"(v));
    return d;
}
__device__ __forceinline__ ull pack2(float lo, float hi) {
    ull d;
    asm("mov.b64 %0, {%1, %2};" : "=l"(d) : "f"(lo), "f"(hi));
    return d;
}
__device__ __forceinline__ float2 unpack2(ull d) {
    float lo, hi;
    asm("mov.b64 {%0, %1}, %2;" : "=f"(lo), "=f"(hi) : "l"(d));
    return make_float2(lo, hi);
}

__global__ void zero_state_kernel() {
    size_t idx = (size_t)blockIdx.x * blockDim.x + threadIdx.x;
    size_t stride = (size_t)gridDim.x * blockDim.x;
    float* h = &g_h[0][0][0];
    float* c = &g_c[0][0][0];
    const size_t n = (size_t)BB * SH_PAD * FF;
    for (size_t i = idx; i < n; i += stride) { h[i] = 0.0f; c[i] = 0.0f; }
}

// Repack weights: row r of the 80-wide reduction.
__global__ void prep_w_kernel(const float* __restrict__ kern,
                              const float* __restrict__ rk) {
    int i = blockIdx.x * blockDim.x + threadIdx.x;
    if (i >= RDIM * FF) return;
    int r = i / FF, f = i % FF;
    const float* src;
    if (r < 16) {
        int k = r >> 3, c = r & 7;
        src = kern + (k * CC + c) * NG;
    } else {
        int rr = r - 16;
        int k = rr >> 5, ff = rr & 31;
        src = rk + (k * FF + ff) * NG;
    }
    g_w4[r][f] = make_float4(src[f], src[32 + f], src[64 + f], src[96 + f]);
}

// Fused up-to-TS timesteps. Grid: (SH/POSB, BB) = (4, 32) = 128 blocks -> 1/SM, one wave.
// smem: w4s 40960B | xsD 33792B | hsD 67840B  -> 142592B
__global__ __launch_bounds__(NTHREADS, 1)
void step_kernel(const float* __restrict__ x, const float* __restrict__ bias,
                 int t0, int ts) {
    extern __shared__ float smem[];
    float4* w4s = (float4*)smem;                     // 2560 float4
    ull*   xsD = (ull*)(smem + RDIM * FF * 4);       // SLOTS*16 duplicated pairs
    ull*   hsD = xsD + SLOTS * 16;                   // HROWS*32 duplicated pairs

    const int b = blockIdx.y;
    const int p0 = blockIdx.x * POSB;
    const int tid = threadIdx.x;

    const int f = tid & 31;
    const int w = tid >> 5;
    const int pl = w * NP;   // warp's local slot base

    // ---- one-time fills
    {
        const float4* wsrc = &g_w4[0][0];
        #pragma unroll
        for (int i = tid; i < RDIM * FF; i += NTHREADS) w4s[i] = wsrc[i];
        const float* hsrc = &g_h[b][p0][0];
        #pragma unroll
        for (int i = tid; i < HROWS * FF; i += NTHREADS) hsD[i] = dup2(hsrc[i]);
        // xs for step 0 (pre-duplicated)
        const size_t base = (((size_t)b * TT + t0) * SS + 2 * p0) * CC;
        #pragma unroll
        for (int i = tid; i < SLOTS * 16; i += NTHREADS) {
            size_t gi = base + i;
            xsD[i] = dup2((gi < (size_t)XTOT) ? x[gi] : 0.0f);
        }
    }

    // ---- c state lives in registers: this thread owns (slot pl+j, filter f)
    // for the whole launch. Coalesced LDG: lanes read g_c[b][p][0..31].
    float creg[NP];
    #pragma unroll
    for (int j = 0; j < NP; j++) {
        const int p = p0 + pl + j;
        creg[j] = g_c[b][p][f];   // p <= 1031 < SH_PAD, pad rows are 0
    }

    const ull b01 = pack2(bias[f], bias[32 + f]);
    const ull b23 = pack2(bias[64 + f], bias[96 + f]);

    __syncthreads();

    for (int s = 0; s < ts; s++) {
        const int width = POSB + (ts - 1 - s);

        // acc[j][0] = packed (gate0,gate1), acc[j][1] = packed (gate2,gate3)
        ull acc[NP][2];
        #pragma unroll
        for (int j = 0; j < NP; j++) { acc[j][0] = b01; acc[j][1] = b23; }

        // ---- x-patch (r = 0..15): 4-row weight groups, duplicated patch pairs
        #pragma unroll
        for (int rg = 0; rg < 4; rg++) {
            ulonglong2 wv0 = *(const ulonglong2*)&w4s[(rg * 4 + 0) * FF + f];
            ulonglong2 wv1 = *(const ulonglong2*)&w4s[(rg * 4 + 1) * FF + f];
            ulonglong2 wv2 = *(const ulonglong2*)&w4s[(rg * 4 + 2) * FF + f];
            ulonglong2 wv3 = *(const ulonglong2*)&w4s[(rg * 4 + 3) * FF + f];
            #pragma unroll
            for (int j = 0; j < NP; j++) {
                ulonglong2 xv01 = *(const ulonglong2*)&xsD[(pl + j) * 16 + rg * 4];
                ulonglong2 xv23 = *(const ulonglong2*)&xsD[(pl + j) * 16 + rg * 4 + 2];
                acc[j][0] = fma2(xv01.x, wv0.x, acc[j][0]);
                acc[j][1] = fma2(xv01.x, wv0.y, acc[j][1]);
                acc[j][0] = fma2(xv01.y, wv1.x, acc[j][0]);
                acc[j][1] = fma2(xv01.y, wv1.y, acc[j][1]);
                acc[j][0] = fma2(xv23.x, wv2.x, acc[j][0]);
                acc[j][1] = fma2(xv23.x, wv2.y, acc[j][1]);
                acc[j][0] = fma2(xv23.y, wv3.x, acc[j][0]);
                acc[j][1] = fma2(xv23.y, wv3.y, acc[j][1]);
            }
        }

        // ---- h-patch: row-major merge of k0/k1 taps; duplicated pairs from smem.
        // h row m feeds slot m via k0 weights and slot m-1 via k1 weights.
        #pragma unroll
        for (int fg = 0; fg < FF / 2; fg++) {
            ulonglong2 w0a = *(const ulonglong2*)&w4s[(16 + fg * 2 + 0) * FF + f];
            ulonglong2 w0b = *(const ulonglong2*)&w4s[(16 + fg * 2 + 1) * FF + f];
            ulonglong2 w1a = *(const ulonglong2*)&w4s[(16 + FF + fg * 2 + 0) * FF + f];
            ulonglong2 w1b = *(const ulonglong2*)&w4s[(16 + FF + fg * 2 + 1) * FF + f];
            #pragma unroll
            for (int m = 0; m <= NP; m++) {
                ulonglong2 hv = *(const ulonglong2*)&hsD[(pl + m) * FF + fg * 2];
                if (m < NP) {
                    acc[m][0] = fma2(hv.x, w0a.x, acc[m][0]);
                    acc[m][1] = fma2(hv.x, w0a.y, acc[m][1]);
                    acc[m][0] = fma2(hv.y, w0b.x, acc[m][0]);
                    acc[m][1] = fma2(hv.y, w0b.y, acc[m][1]);
                }
                if (m > 0) {
                    acc[m - 1][0] = fma2(hv.x, w1a.x, acc[m - 1][0]);
                    acc[m - 1][1] = fma2(hv.x, w1a.y, acc[m - 1][1]);
                    acc[m - 1][0] = fma2(hv.y, w1b.x, acc[m - 1][0]);
                    acc[m - 1][1] = fma2(hv.y, w1b.y, acc[m - 1][1]);
                }
            }
        }

        __syncthreads();   // all reads of hsD / xsD complete

        // ---- cell update: c in registers, in-place h write (masked)
        #pragma unroll
        for (int j = 0; j < NP; j++) {
            const int m = pl + j;
            const int p = p0 + m;
            float cold = creg[j];
            float2 a01 = unpack2(acc[j][0]);   // (zi, zf)
            float2 a23 = unpack2(acc[j][1]);   // (zc, zo)
            float i_g = hsig(a01.x);
            float f_g = hsig(a01.y);
            float cn = f_g * cold + i_g * ftanh(a23.x);
            float o_g = hsig(a23.y);
            float hn = o_g * ftanh(cn);
            bool ok = (m < width) && (p < SH);
            hsD[m * FF + f] = dup2(ok ? hn : 0.0f);
            creg[j] = ok ? cn : cold;
        }

        // ---- prefetch xs for next step (xs readers finished at barrier above)
        if (s + 1 < ts) {
            const size_t base = (((size_t)b * TT + (t0 + s + 1)) * SS + 2 * p0) * CC;
            #pragma unroll
            for (int i = tid; i < SLOTS * 16; i += NTHREADS) {
                size_t gi = base + i;
                xsD[i] = dup2((gi < (size_t)XTOT) ? x[gi] : 0.0f);
            }
        }
        __syncthreads();   // h/xs writes visible
    }

    // ---- writeback owned rows (h from smem, c from registers)
    #pragma unroll
    for (int j = 0; j < NP; j++) {
        const int m = pl + j;
        if (m < POSB) {
            g_h[b][p0 + m][f] = unpack2(hsD[m * FF + f]).x;
            g_c[b][p0 + m][f] = creg[j];
        }
    }
}

// out[b] = sum(h_final[b] * dense_w) + dense_b
__global__ __launch_bounds__(256)
void dense_kernel(const float* __restrict__ dw, const float* __restrict__ db,
                  float* __restrict__ out) {
    const int b = blockIdx.x;
    const float* h = &g_h[b][0][0];   // rows 0..SH-1 contiguous
    float s = 0.0f;
    for (int i = threadIdx.x; i < SH * FF; i += 256) s += h[i] * dw[i];
    #pragma unroll
    for (int off = 16; off > 0; off >>= 1) s += __shfl_down_sync(0xffffffffu, s, off);
    __shared__ float red[8];
    int lane = threadIdx.x & 31, wid = threadIdx.x >> 5;
    if (lane == 0) red[wid] = s;
    __syncthreads();
    if (wid == 0) {
        s = (lane < 8) ? red[lane] : 0.0f;
        #pragma unroll
        for (int off = 4; off > 0; off >>= 1) s += __shfl_down_sync(0xffffffffu, s, off);
        if (lane == 0) out[b] = s + db[0];
    }
}

extern "C" void kernel_launch(void* const* d_in, const int* in_sizes, int n_in,
                              void* d_out, int out_size) {
    const float* x    = (const float*)d_in[0];  // (32,50,2048,8)
    const float* kern = (const float*)d_in[1];  // (2,8,128)
    const float* rk   = (const float*)d_in[2];  // (2,32,128)
    const float* bias = (const float*)d_in[3];  // (128,)
    const float* dw   = (const float*)d_in[4];  // (32768,1)
    const float* db   = (const float*)d_in[5];  // (1,)
    float* out = (float*)d_out;                  // (32,1)

    const int smem_bytes = RDIM * FF * 16 + SLOTS * 16 * 8 + HROWS * FF * 8;
    static int configured = 0;
    if (!configured) {
        cudaFuncSetAttribute(step_kernel, cudaFuncAttributeMaxDynamicSharedMemorySize,
                             smem_bytes);
        configured = 1;
    }

    zero_state_kernel<<<512, 256>>>();
    prep_w_kernel<<<(RDIM * FF + 255) / 256, 256>>>(kern, rk);

    dim3 grid(SH / POSB, BB);
    for (int t0 = 0; t0 < TT; t0 += TS) {
        int ts = (TT - t0 < TS) ? (TT - t0) : TS;
        step_kernel<<<grid, NTHREADS, smem_bytes>>>(x, bias, t0, ts);
    }
    dense_kernel<<<BB, 256>>>(dw, db, out);
}

// round 13
// speedup vs baseline: 1.0005x; 1.0005x over previous
#include <cuda_runtime.h>
#include <math.h>

#define BB 32
#define TT 50
#define SS 2048
#define CC 8
#define FF 32
#define SH 1024
#define SH_PAD 1056     // SH + 32 zero pad rows (halo reads reach 1032)
#define NG 128          // 4*F gates
#define RDIM 80         // 16 (x patch) + 64 (h patch)
#define POSB 256        // owned output positions per block
#define TS 8            // max fused timesteps per launch
#define NWARPS 24       // multiple of 4: balanced SMSPs
#define NP 11           // slots per warp
#define SLOTS (NWARPS*NP)   // 264 computed slots (wedge needs 256+7=263)
#define NTHREADS 768
#define HROWS 265       // smem h rows (reads reach row 264)
#define XS_F (SLOTS*16) // 4224 floats per x buffer
#define XTOT (BB*TT*SS*CC)

typedef unsigned long long ull;

// Persistent device state (zeroed every kernel_launch call; pad rows stay 0)
__device__ float g_h[BB][SH_PAD][FF];
__device__ float g_c[BB][SH_PAD][FF];
__device__ float4 g_w4[RDIM][FF];          // [r][f] -> (gate0, gate1, gate2, gate3)

__device__ __forceinline__ float hsig(float x) {
    return __saturatef(fmaf(x, 0.2f, 0.5f));
}

// fast tanh: 1 - 2/(exp(2x)+1); abs err ~1e-6, exact saturation
__device__ __forceinline__ float ftanh(float x) {
    float e = __expf(2.0f * x);
    return 1.0f - __fdividef(2.0f, e + 1.0f);
}

// packed f32x2 helpers
__device__ __forceinline__ ull fma2(ull a, ull b, ull c) {
    ull d;
    asm("fma.rn.f32x2 %0, %1, %2, %3;" : "=l"(d) : "l"(a), "l"(b), "l"(c));
    return d;
}
__device__ __forceinline__ ull dup2(float v) {
    ull d;
    asm("mov.b64 %0, {%1, %1};" : "=l"(d) : "f"(v));
    return d;
}
__device__ __forceinline__ ull pack2(float lo, float hi) {
    ull d;
    asm("mov.b64 %0, {%1, %2};" : "=l"(d) : "f"(lo), "f"(hi));
    return d;
}
__device__ __forceinline__ float2 unpack2(ull d) {
    float lo, hi;
    asm("mov.b64 {%0, %1}, %2;" : "=f"(lo), "=f"(hi) : "l"(d));
    return make_float2(lo, hi);
}

__global__ void zero_state_kernel() {
    size_t idx = (size_t)blockIdx.x * blockDim.x + threadIdx.x;
    size_t stride = (size_t)gridDim.x * blockDim.x;
    float* h = &g_h[0][0][0];
    float* c = &g_c[0][0][0];
    const size_t n = (size_t)BB * SH_PAD * FF;
    for (size_t i = idx; i < n; i += stride) { h[i] = 0.0f; c[i] = 0.0f; }
}

// Repack weights: row r of the 80-wide reduction.
__global__ void prep_w_kernel(const float* __restrict__ kern,
                              const float* __restrict__ rk) {
    int i = blockIdx.x * blockDim.x + threadIdx.x;
    if (i >= RDIM * FF) return;
    int r = i / FF, f = i % FF;
    const float* src;
    if (r < 16) {
        int k = r >> 3, c = r & 7;
        src = kern + (k * CC + c) * NG;
    } else {
        int rr = r - 16;
        int k = rr >> 5, ff = rr & 31;
        src = rk + (k * FF + ff) * NG;
    }
    g_w4[r][f] = make_float4(src[f], src[32 + f], src[64 + f], src[96 + f]);
}

// Fused up-to-TS timesteps. Grid: (SH/POSB, BB) = (4, 32) = 128 blocks -> 1/SM, one wave.
// smem: w4s 40960B | xs0/xs1 2*16896B | hs0/hs1 2*67840B  -> 210432B
__global__ __launch_bounds__(NTHREADS, 1)
void step_kernel(const float* __restrict__ x, const float* __restrict__ bias,
                 int t0, int ts) {
    extern __shared__ float smem[];
    float4* w4s = (float4*)smem;                         // 2560 float4
    float* xs0 = smem + RDIM * FF * 4;                   // XS_F floats
    float* xs1 = xs0 + XS_F;                             // XS_F floats
    ull* hs0 = (ull*)(xs1 + XS_F);                       // HROWS*FF pairs
    ull* hs1 = hs0 + HROWS * FF;

    const int b = blockIdx.y;
    const int p0 = blockIdx.x * POSB;
    const int tid = threadIdx.x;
    const int f = tid & 31;
    const int w = tid >> 5;
    const int pl = w * NP;   // warp's local slot base

    // ---- one-time fills
    {
        const float4* wsrc = &g_w4[0][0];
        #pragma unroll
        for (int i = tid; i < RDIM * FF; i += NTHREADS) w4s[i] = wsrc[i];
        const float* hsrc = &g_h[b][p0][0];
        #pragma unroll
        for (int i = tid; i < HROWS * FF; i += NTHREADS) hs0[i] = dup2(hsrc[i]);
        if (tid < FF) hs1[(HROWS - 1) * FF + tid] = 0;   // hs1 halo row (never written)
        // x buffer 0 for step 0 (float4, guarded)
        const int base4 = ((((b * TT) + t0) * SS + 2 * p0) * CC) >> 2;
        #pragma unroll
        for (int i = tid; i < XS_F / 4; i += NTHREADS) {
            int gi = base4 + i;
            ((float4*)xs0)[i] = (gi < XTOT / 4) ? ((const float4*)x)[gi]
                                                : make_float4(0.f, 0.f, 0.f, 0.f);
        }
    }

    // ---- c state in registers: thread owns (slot pl+j, filter f) all launch
    float creg[NP];
    #pragma unroll
    for (int j = 0; j < NP; j++) creg[j] = g_c[b][p0 + pl + j][f];

    const ull b01 = pack2(bias[f], bias[32 + f]);
    const ull b23 = pack2(bias[64 + f], bias[96 + f]);

    float* xsA = xs0;  float* xsB = xs1;   // read A, prefetch B
    ull* hcur = hs0;   ull* hnxt = hs1;    // read cur, write nxt

    __syncthreads();

    for (int s = 0; s < ts; s++) {
        const int width = POSB + (ts - 1 - s);

        // acc[j][0] = packed (gate0,gate1), acc[j][1] = packed (gate2,gate3)
        ull acc[NP][2];
        #pragma unroll
        for (int j = 0; j < NP; j++) { acc[j][0] = b01; acc[j][1] = b23; }

        // ---- x-patch (r = 0..15): 2-row weight groups, float2 broadcast patches
        #pragma unroll
        for (int rg = 0; rg < 8; rg++) {
            ulonglong2 wa = *(const ulonglong2*)&w4s[(rg * 2 + 0) * FF + f];
            ulonglong2 wb = *(const ulonglong2*)&w4s[(rg * 2 + 1) * FF + f];
            #pragma unroll
            for (int j = 0; j < NP; j++) {
                float2 pv = *(const float2*)&xsA[(pl + j) * 16 + rg * 2];
                ull d0 = dup2(pv.x);
                ull d1 = dup2(pv.y);
                acc[j][0] = fma2(d0, wa.x, acc[j][0]);
                acc[j][1] = fma2(d0, wa.y, acc[j][1]);
                acc[j][0] = fma2(d1, wb.x, acc[j][0]);
                acc[j][1] = fma2(d1, wb.y, acc[j][1]);
            }
        }

        // ---- h-patch: row-major merge of k0/k1 taps; duplicated pairs from smem.
        #pragma unroll
        for (int fg = 0; fg < FF / 2; fg++) {
            ulonglong2 w0a = *(const ulonglong2*)&w4s[(16 + fg * 2 + 0) * FF + f];
            ulonglong2 w0b = *(const ulonglong2*)&w4s[(16 + fg * 2 + 1) * FF + f];
            ulonglong2 w1a = *(const ulonglong2*)&w4s[(16 + FF + fg * 2 + 0) * FF + f];
            ulonglong2 w1b = *(const ulonglong2*)&w4s[(16 + FF + fg * 2 + 1) * FF + f];
            #pragma unroll
            for (int m = 0; m <= NP; m++) {
                ulonglong2 hv = *(const ulonglong2*)&hcur[(pl + m) * FF + fg * 2];
                if (m < NP) {
                    acc[m][0] = fma2(hv.x, w0a.x, acc[m][0]);
                    acc[m][1] = fma2(hv.x, w0a.y, acc[m][1]);
                    acc[m][0] = fma2(hv.y, w0b.x, acc[m][0]);
                    acc[m][1] = fma2(hv.y, w0b.y, acc[m][1]);
                }
                if (m > 0) {
                    acc[m - 1][0] = fma2(hv.x, w1a.x, acc[m - 1][0]);
                    acc[m - 1][1] = fma2(hv.x, w1a.y, acc[m - 1][1]);
                    acc[m - 1][0] = fma2(hv.y, w1b.x, acc[m - 1][0]);
                    acc[m - 1][1] = fma2(hv.y, w1b.y, acc[m - 1][1]);
                }
            }
        }

        // ---- cell update: c in regs, h -> hnxt (no conflict with hcur reads)
        #pragma unroll
        for (int j = 0; j < NP; j++) {
            const int m = pl + j;
            const int p = p0 + m;
            float cold = creg[j];
            float2 a01 = unpack2(acc[j][0]);   // (zi, zf)
            float2 a23 = unpack2(acc[j][1]);   // (zc, zo)
            float i_g = hsig(a01.x);
            float f_g = hsig(a01.y);
            float cn = f_g * cold + i_g * ftanh(a23.x);
            float o_g = hsig(a23.y);
            float hn = o_g * ftanh(cn);
            bool ok = (m < width) && (p < SH);
            hnxt[m * FF + f] = dup2(ok ? hn : 0.0f);
            creg[j] = ok ? cn : cold;
        }

        // ---- prefetch x for next step into the other x buffer (no conflict)
        if (s + 1 < ts) {
            const int base4 = ((((b * TT) + (t0 + s + 1)) * SS + 2 * p0) * CC) >> 2;
            #pragma unroll
            for (int i = tid; i < XS_F / 4; i += NTHREADS) {
                int gi = base4 + i;
                ((float4*)xsB)[i] = (gi < XTOT / 4) ? ((const float4*)x)[gi]
                                                    : make_float4(0.f, 0.f, 0.f, 0.f);
            }
        }

        __syncthreads();   // single full-stop barrier per step
        { ull* t = hcur; hcur = hnxt; hnxt = t; }
        { float* t = xsA; xsA = xsB; xsB = t; }
    }

    // ---- writeback owned rows (h from hcur, c from registers)
    #pragma unroll
    for (int j = 0; j < NP; j++) {
        const int m = pl + j;
        if (m < POSB) {
            g_h[b][p0 + m][f] = unpack2(hcur[m * FF + f]).x;
            g_c[b][p0 + m][f] = creg[j];
        }
    }
}

// out[b] = sum(h_final[b] * dense_w) + dense_b
__global__ __launch_bounds__(256)
void dense_kernel(const float* __restrict__ dw, const float* __restrict__ db,
                  float* __restrict__ out) {
    const int b = blockIdx.x;
    const float* h = &g_h[b][0][0];   // rows 0..SH-1 contiguous
    float s = 0.0f;
    for (int i = threadIdx.x; i < SH * FF; i += 256) s += h[i] * dw[i];
    #pragma unroll
    for (int off = 16; off > 0; off >>= 1) s += __shfl_down_sync(0xffffffffu, s, off);
    __shared__ float red[8];
    int lane = threadIdx.x & 31, wid = threadIdx.x >> 5;
    if (lane == 0) red[wid] = s;
    __syncthreads();
    if (wid == 0) {
        s = (lane < 8) ? red[lane] : 0.0f;
        #pragma unroll
        for (int off = 4; off > 0; off >>= 1) s += __shfl_down_sync(0xffffffffu, s, off);
        if (lane == 0) out[b] = s + db[0];
    }
}

extern "C" void kernel_launch(void* const* d_in, const int* in_sizes, int n_in,
                              void* d_out, int out_size) {
    const float* x    = (const float*)d_in[0];  // (32,50,2048,8)
    const float* kern = (const float*)d_in[1];  // (2,8,128)
    const float* rk   = (const float*)d_in[2];  // (2,32,128)
    const float* bias = (const float*)d_in[3];  // (128,)
    const float* dw   = (const float*)d_in[4];  // (32768,1)
    const float* db   = (const float*)d_in[5];  // (1,)
    float* out = (float*)d_out;                  // (32,1)

    const int smem_bytes = RDIM * FF * 16 + 2 * XS_F * 4 + 2 * HROWS * FF * 8; // 210432
    static int configured = 0;
    if (!configured) {
        cudaFuncSetAttribute(step_kernel, cudaFuncAttributeMaxDynamicSharedMemorySize,
                             smem_bytes);
        configured = 1;
    }

    zero_state_kernel<<<512, 256>>>();
    prep_w_kernel<<<(RDIM * FF + 255) / 256, 256>>>(kern, rk);

    dim3 grid(SH / POSB, BB);
    for (int t0 = 0; t0 < TT; t0 += TS) {
        int ts = (TT - t0 < TS) ? (TT - t0) : TS;
        step_kernel<<<grid, NTHREADS, smem_bytes>>>(x, bias, t0, ts);
    }
    dense_kernel<<<BB, 256>>>(dw, db, out);
}

// round 14
// speedup vs baseline: 1.1348x; 1.1342x over previous
#include <cuda_runtime.h>
#include <math.h>

#define BB 32
#define TT 50
#define SS 2048
#define CC 8
#define FF 32
#define SH 1024
#define NG 128          // 4*F gates
#define RDIM 80         // 16 (x patch) + 64 (h patch)
#define POSB 256        // owned output positions per CTA
#define NWARPS 16
#define NP 16           // slots per warp (16*16 = 256, exact)
#define NTHREADS 512
#define HROWS 258       // 256 owned rows + 2 parity halo rows
#define XS_N (POSB*16)  // 4096 x entries per step
#define CLUSTER_X 4

typedef unsigned long long ull;

// Only the final h is ever in global memory (for the dense reduction).
__device__ float g_h[BB][SH][FF];

__device__ __forceinline__ float hsig(float x) {
    return __saturatef(fmaf(x, 0.2f, 0.5f));
}

// fast tanh: 1 - 2/(exp(2x)+1); abs err ~1e-6, exact saturation
__device__ __forceinline__ float ftanh(float x) {
    float e = __expf(2.0f * x);
    return 1.0f - __fdividef(2.0f, e + 1.0f);
}

__device__ __forceinline__ ull fma2(ull a, ull b, ull c) {
    ull d;
    asm("fma.rn.f32x2 %0, %1, %2, %3;" : "=l"(d) : "l"(a), "l"(b), "l"(c));
    return d;
}
__device__ __forceinline__ ull dup2(float v) {
    ull d;
    asm("mov.b64 %0, {%1, %1};" : "=l"(d) : "f"(v));
    return d;
}
__device__ __forceinline__ ull pack2(float lo, float hi) {
    ull d;
    asm("mov.b64 %0, {%1, %2};" : "=l"(d) : "f"(lo), "f"(hi));
    return d;
}
__device__ __forceinline__ float2 unpack2(ull d) {
    float lo, hi;
    asm("mov.b64 {%0, %1}, %2;" : "=f"(lo), "=f"(hi) : "l"(d));
    return make_float2(lo, hi);
}
__device__ __forceinline__ unsigned smem_u32(const void* p) {
    unsigned a;
    asm("{ .reg .u64 t; cvta.to.shared.u64 t, %1; cvt.u32.u64 %0, t; }"
        : "=r"(a) : "l"(p));
    return a;
}

// All 50 timesteps in ONE launch. Grid (4, 32) = 128 CTAs, cluster (4,1,1)
// = one batch per cluster. Halo h row exchanged via DSMEM each step.
// smem: w4s 40960B | xsD 32768B | hsD 258*32*8 = 66048B  -> 139776B
__global__ __launch_bounds__(NTHREADS, 1) __cluster_dims__(CLUSTER_X, 1, 1)
void lstm_kernel(const float* __restrict__ x, const float* __restrict__ kern,
                 const float* __restrict__ rk, const float* __restrict__ bias) {
    extern __shared__ float smem[];
    float4* w4s = (float4*)smem;                 // 2560 float4
    ull* xsD = (ull*)(smem + RDIM * FF * 4);     // XS_N duplicated pairs
    ull* hsD = xsD + XS_N;                       // HROWS*FF duplicated pairs

    const int b = blockIdx.y;
    const int rank = blockIdx.x;                 // == cluster cta rank (grid.x == 4)
    const int p0 = rank * POSB;
    const int tid = threadIdx.x;
    const int f = tid & 31;
    const int w = tid >> 5;
    const int pl = w * NP;

    // ---- build weights in smem from global (once for all 50 steps)
    for (int i = tid; i < RDIM * FF; i += NTHREADS) {
        int r = i >> 5, ff = i & 31;
        const float* src;
        if (r < 16) {
            src = kern + ((r >> 3) * CC + (r & 7)) * NG;
        } else {
            int rr = r - 16;
            src = rk + ((rr >> 5) * FF + (rr & 31)) * NG;
        }
        w4s[i] = make_float4(src[ff], src[32 + ff], src[64 + ff], src[96 + ff]);
    }
    // ---- h state = 0 (incl. both halo parity rows)
    for (int i = tid; i < HROWS * FF; i += NTHREADS) hsD[i] = 0ULL;
    // ---- x tile for t = 0 (pre-duplicated pairs)
    {
        const float4* xsrc = (const float4*)(x + ((size_t)(b * TT) * SS + 2 * p0) * CC);
        for (int i = tid; i < XS_N / 4; i += NTHREADS) {
            float4 v = xsrc[i];
            xsD[i * 4 + 0] = dup2(v.x); xsD[i * 4 + 1] = dup2(v.y);
            xsD[i * 4 + 2] = dup2(v.z); xsD[i * 4 + 3] = dup2(v.w);
        }
    }
    // ---- c state in registers for the whole sequence
    float creg[NP];
    #pragma unroll
    for (int j = 0; j < NP; j++) creg[j] = 0.0f;

    const ull b01 = pack2(bias[f], bias[32 + f]);
    const ull b23 = pack2(bias[64 + f], bias[96 + f]);

    // init must be cluster-visible before any halo push lands
    asm volatile("barrier.cluster.arrive.aligned;" ::: "memory");
    asm volatile("barrier.cluster.wait.aligned;" ::: "memory");

    for (int t = 0; t < TT; t++) {
        ull acc[NP][2];
        #pragma unroll
        for (int j = 0; j < NP; j++) { acc[j][0] = b01; acc[j][1] = b23; }

        // ---- x-patch (r = 0..15): 4-row weight groups, pre-duplicated pairs
        #pragma unroll
        for (int rg = 0; rg < 4; rg++) {
            ulonglong2 wv0 = *(const ulonglong2*)&w4s[(rg * 4 + 0) * FF + f];
            ulonglong2 wv1 = *(const ulonglong2*)&w4s[(rg * 4 + 1) * FF + f];
            ulonglong2 wv2 = *(const ulonglong2*)&w4s[(rg * 4 + 2) * FF + f];
            ulonglong2 wv3 = *(const ulonglong2*)&w4s[(rg * 4 + 3) * FF + f];
            #pragma unroll
            for (int j = 0; j < NP; j++) {
                ulonglong2 xv01 = *(const ulonglong2*)&xsD[(pl + j) * 16 + rg * 4];
                ulonglong2 xv23 = *(const ulonglong2*)&xsD[(pl + j) * 16 + rg * 4 + 2];
                acc[j][0] = fma2(xv01.x, wv0.x, acc[j][0]);
                acc[j][1] = fma2(xv01.x, wv0.y, acc[j][1]);
                acc[j][0] = fma2(xv01.y, wv1.x, acc[j][0]);
                acc[j][1] = fma2(xv01.y, wv1.y, acc[j][1]);
                acc[j][0] = fma2(xv23.x, wv2.x, acc[j][0]);
                acc[j][1] = fma2(xv23.x, wv2.y, acc[j][1]);
                acc[j][0] = fma2(xv23.y, wv3.x, acc[j][0]);
                acc[j][1] = fma2(xv23.y, wv3.y, acc[j][1]);
            }
        }

        // ---- h-patch: row-major merged k0/k1 taps. Row m feeds slot m (k0)
        // and slot m-1 (k1). Last warp's top row is the parity halo row.
        const int lastrow = (w == NWARPS - 1) ? (256 + (t & 1)) : (pl + NP);
        #pragma unroll
        for (int fg = 0; fg < FF / 2; fg++) {
            ulonglong2 w0a = *(const ulonglong2*)&w4s[(16 + fg * 2 + 0) * FF + f];
            ulonglong2 w0b = *(const ulonglong2*)&w4s[(16 + fg * 2 + 1) * FF + f];
            ulonglong2 w1a = *(const ulonglong2*)&w4s[(16 + FF + fg * 2 + 0) * FF + f];
            ulonglong2 w1b = *(const ulonglong2*)&w4s[(16 + FF + fg * 2 + 1) * FF + f];
            #pragma unroll
            for (int m = 0; m <= NP; m++) {
                const int row = (m == NP) ? lastrow : (pl + m);
                ulonglong2 hv = *(const ulonglong2*)&hsD[row * FF + fg * 2];
                if (m < NP) {
                    acc[m][0] = fma2(hv.x, w0a.x, acc[m][0]);
                    acc[m][1] = fma2(hv.x, w0a.y, acc[m][1]);
                    acc[m][0] = fma2(hv.y, w0b.x, acc[m][0]);
                    acc[m][1] = fma2(hv.y, w0b.y, acc[m][1]);
                }
                if (m > 0) {
                    acc[m - 1][0] = fma2(hv.x, w1a.x, acc[m - 1][0]);
                    acc[m - 1][1] = fma2(hv.x, w1a.y, acc[m - 1][1]);
                    acc[m - 1][0] = fma2(hv.y, w1b.x, acc[m - 1][0]);
                    acc[m - 1][1] = fma2(hv.y, w1b.y, acc[m - 1][1]);
                }
            }
        }

        __syncthreads();   // all hsD/xsD reads complete before writes

        // ---- cell update (c in regs), halo push to left neighbor via DSMEM
        #pragma unroll
        for (int j = 0; j < NP; j++) {
            const int m = pl + j;
            float2 a01 = unpack2(acc[j][0]);   // (zi, zf)
            float2 a23 = unpack2(acc[j][1]);   // (zc, zo)
            float i_g = hsig(a01.x);
            float f_g = hsig(a01.y);
            float cn = f_g * creg[j] + i_g * ftanh(a23.x);
            float hn = hsig(a23.y) * ftanh(cn);
            creg[j] = cn;
            ull hd = dup2(hn);
            hsD[m * FF + f] = hd;
            if (m == 0 && rank > 0) {
                // value produced at step t is read at step t+1 -> parity (t+1)&1
                unsigned la = smem_u32(&hsD[(256 + ((t + 1) & 1)) * FF + f]);
                unsigned ra;
                asm("mapa.shared::cluster.u32 %0, %1, %2;"
                    : "=r"(ra) : "r"(la), "r"(rank - 1));
                asm volatile("st.shared::cluster.u64 [%0], %1;"
                             :: "r"(ra), "l"(hd) : "memory");
            }
        }

        // ---- prefetch x for step t+1 (readers finished at the barrier above)
        if (t + 1 < TT) {
            const float4* xsrc =
                (const float4*)(x + ((size_t)(b * TT + t + 1) * SS + 2 * p0) * CC);
            for (int i = tid; i < XS_N / 4; i += NTHREADS) {
                float4 v = xsrc[i];
                xsD[i * 4 + 0] = dup2(v.x); xsD[i * 4 + 1] = dup2(v.y);
                xsD[i * 4 + 2] = dup2(v.z); xsD[i * 4 + 3] = dup2(v.w);
            }
        }

        // cluster-wide: orders local h/x writes AND the remote halo push
        asm volatile("barrier.cluster.arrive.aligned;" ::: "memory");
        asm volatile("barrier.cluster.wait.aligned;" ::: "memory");
    }

    // ---- final h to global for the dense reduction
    #pragma unroll
    for (int j = 0; j < NP; j++) {
        const int m = pl + j;
        g_h[b][p0 + m][f] = unpack2(hsD[m * FF + f]).x;
    }
}

// out[b] = sum(h_final[b] * dense_w) + dense_b
__global__ __launch_bounds__(256)
void dense_kernel(const float* __restrict__ dw, const float* __restrict__ db,
                  float* __restrict__ out) {
    const int b = blockIdx.x;
    const float* h = &g_h[b][0][0];
    float s = 0.0f;
    for (int i = threadIdx.x; i < SH * FF; i += 256) s += h[i] * dw[i];
    #pragma unroll
    for (int off = 16; off > 0; off >>= 1) s += __shfl_down_sync(0xffffffffu, s, off);
    __shared__ float red[8];
    int lane = threadIdx.x & 31, wid = threadIdx.x >> 5;
    if (lane == 0) red[wid] = s;
    __syncthreads();
    if (wid == 0) {
        s = (lane < 8) ? red[lane] : 0.0f;
        #pragma unroll
        for (int off = 4; off > 0; off >>= 1) s += __shfl_down_sync(0xffffffffu, s, off);
        if (lane == 0) out[b] = s + db[0];
    }
}

extern "C" void kernel_launch(void* const* d_in, const int* in_sizes, int n_in,
                              void* d_out, int out_size) {
    const float* x    = (const float*)d_in[0];  // (32,50,2048,8)
    const float* kern = (const float*)d_in[1];  // (2,8,128)
    const float* rk   = (const float*)d_in[2];  // (2,32,128)
    const float* bias = (const float*)d_in[3];  // (128,)
    const float* dw   = (const float*)d_in[4];  // (32768,1)
    const float* db   = (const float*)d_in[5];  // (1,)
    float* out = (float*)d_out;                  // (32,1)

    const int smem_bytes = RDIM * FF * 16 + XS_N * 8 + HROWS * FF * 8; // 139776
    static int configured = 0;
    if (!configured) {
        cudaFuncSetAttribute(lstm_kernel, cudaFuncAttributeMaxDynamicSharedMemorySize,
                             smem_bytes);
        configured = 1;
    }

    dim3 grid(CLUSTER_X, BB);   // 128 CTAs = 32 clusters of 4 (one batch each)
    lstm_kernel<<<grid, NTHREADS, smem_bytes>>>(x, kern, rk, bias);
    dense_kernel<<<BB, 256>>>(dw, db, out);
}

// round 15
// speedup vs baseline: 1.1696x; 1.0307x over previous
#include <cuda_runtime.h>
#include <math.h>

#define BB 32
#define TT 50
#define SS 2048
#define CC 8
#define FF 32
#define SH 1024
#define NG 128          // 4*F gates
#define RDIM 80         // 16 (x patch) + 64 (h patch)
#define POSB 256        // owned output positions per CTA
#define NWARPS 16
#define NP 16           // slots per warp (16*16 = 256, exact)
#define NTHREADS 512
#define HROWS 257       // 256 owned rows + 1 halo row (per parity buffer)
#define HBUF (HROWS*FF) // ull entries per parity buffer
#define XS_N (POSB*16)  // 4096 x entries per step
#define CLUSTER_X 4

typedef unsigned long long ull;

__device__ __forceinline__ float hsig(float x) {
    return __saturatef(fmaf(x, 0.2f, 0.5f));
}

// fast tanh: 1 - 2/(exp(2x)+1); abs err ~1e-6, exact saturation
__device__ __forceinline__ float ftanh(float x) {
    float e = __expf(2.0f * x);
    return 1.0f - __fdividef(2.0f, e + 1.0f);
}

__device__ __forceinline__ ull fma2(ull a, ull b, ull c) {
    ull d;
    asm("fma.rn.f32x2 %0, %1, %2, %3;" : "=l"(d) : "l"(a), "l"(b), "l"(c));
    return d;
}
__device__ __forceinline__ ull dup2(float v) {
    ull d;
    asm("mov.b64 %0, {%1, %1};" : "=l"(d) : "f"(v));
    return d;
}
__device__ __forceinline__ ull pack2(float lo, float hi) {
    ull d;
    asm("mov.b64 %0, {%1, %2};" : "=l"(d) : "f"(lo), "f"(hi));
    return d;
}
__device__ __forceinline__ float2 unpack2(ull d) {
    float lo, hi;
    asm("mov.b64 {%0, %1}, %2;" : "=f"(lo), "=f"(hi) : "l"(d));
    return make_float2(lo, hi);
}
__device__ __forceinline__ unsigned smem_u32(const void* p) {
    unsigned a;
    asm("{ .reg .u64 t; cvta.to.shared.u64 t, %1; cvt.u32.u64 %0, t; }"
        : "=r"(a) : "l"(p));
    return a;
}

// out[b] = db[0] before lstm_kernel atomically accumulates the dense dot.
__global__ void init_out_kernel(const float* __restrict__ db, float* __restrict__ out) {
    if (threadIdx.x < BB) out[threadIdx.x] = db[0];
}

// All 50 timesteps + fused Dense(1) in ONE launch.
// Grid (4, 32) = 128 CTAs; cluster (4,1,1) = one batch per cluster.
// smem: w4s 40960B | xsD 32768B | hsD 2*257*32*8 = 131584B -> 205312B
__global__ __launch_bounds__(NTHREADS, 1) __cluster_dims__(CLUSTER_X, 1, 1)
void lstm_kernel(const float* __restrict__ x, const float* __restrict__ kern,
                 const float* __restrict__ rk, const float* __restrict__ bias,
                 const float* __restrict__ dw, float* __restrict__ out) {
    extern __shared__ float smem[];
    float4* w4s = (float4*)smem;                 // 2560 float4
    ull* xsD = (ull*)(smem + RDIM * FF * 4);     // XS_N duplicated pairs
    ull* hsD = xsD + XS_N;                       // 2 parity buffers of HBUF

    const int b = blockIdx.y;
    const int rank = blockIdx.x;                 // cluster cta rank (grid.x == 4)
    const int p0 = rank * POSB;
    const int tid = threadIdx.x;
    const int f = tid & 31;
    const int w = tid >> 5;
    const int pl = w * NP;

    // ---- build weights in smem (once for all 50 steps)
    for (int i = tid; i < RDIM * FF; i += NTHREADS) {
        int r = i >> 5, ff = i & 31;
        const float* src;
        if (r < 16) {
            src = kern + ((r >> 3) * CC + (r & 7)) * NG;
        } else {
            int rr = r - 16;
            src = rk + ((rr >> 5) * FF + (rr & 31)) * NG;
        }
        w4s[i] = make_float4(src[ff], src[32 + ff], src[64 + ff], src[96 + ff]);
    }
    // ---- h state = 0 (both parity buffers incl. halo rows)
    for (int i = tid; i < 2 * HBUF; i += NTHREADS) hsD[i] = 0ULL;
    // ---- x tile for t = 0 (pre-duplicated pairs, warp-local pattern)
    {
        const float4* xsrc = (const float4*)(x + ((size_t)(b * TT) * SS + 2 * p0) * CC);
        int i0 = pl * 4 + (f) * 2;   // two float4 per lane, warp-private region
        #pragma unroll
        for (int q = 0; q < 2; q++) {
            float4 v = xsrc[i0 + q];
            xsD[(i0 + q) * 4 + 0] = dup2(v.x);
            xsD[(i0 + q) * 4 + 1] = dup2(v.y);
            xsD[(i0 + q) * 4 + 2] = dup2(v.z);
            xsD[(i0 + q) * 4 + 3] = dup2(v.w);
        }
    }
    // ---- c state in registers for the whole sequence
    float creg[NP];
    #pragma unroll
    for (int j = 0; j < NP; j++) creg[j] = 0.0f;

    const ull b01 = pack2(bias[f], bias[32 + f]);
    const ull b23 = pack2(bias[64 + f], bias[96 + f]);

    // init (incl. remote-targeted halo rows) must be cluster-visible
    asm volatile("barrier.cluster.arrive.aligned;" ::: "memory");
    asm volatile("barrier.cluster.wait.aligned;" ::: "memory");

    for (int t = 0; t < TT; t++) {
        const int par = t & 1;
        ull* hrd = hsD + par * HBUF;          // read current h
        ull* hwr = hsD + (par ^ 1) * HBUF;    // write next h

        ull acc[NP][2];
        #pragma unroll
        for (int j = 0; j < NP; j++) { acc[j][0] = b01; acc[j][1] = b23; }

        // ---- x-patch (r = 0..15): 4-row weight groups, pre-duplicated pairs
        #pragma unroll
        for (int rg = 0; rg < 4; rg++) {
            ulonglong2 wv0 = *(const ulonglong2*)&w4s[(rg * 4 + 0) * FF + f];
            ulonglong2 wv1 = *(const ulonglong2*)&w4s[(rg * 4 + 1) * FF + f];
            ulonglong2 wv2 = *(const ulonglong2*)&w4s[(rg * 4 + 2) * FF + f];
            ulonglong2 wv3 = *(const ulonglong2*)&w4s[(rg * 4 + 3) * FF + f];
            #pragma unroll
            for (int j = 0; j < NP; j++) {
                ulonglong2 xv01 = *(const ulonglong2*)&xsD[(pl + j) * 16 + rg * 4];
                ulonglong2 xv23 = *(const ulonglong2*)&xsD[(pl + j) * 16 + rg * 4 + 2];
                acc[j][0] = fma2(xv01.x, wv0.x, acc[j][0]);
                acc[j][1] = fma2(xv01.x, wv0.y, acc[j][1]);
                acc[j][0] = fma2(xv01.y, wv1.x, acc[j][0]);
                acc[j][1] = fma2(xv01.y, wv1.y, acc[j][1]);
                acc[j][0] = fma2(xv23.x, wv2.x, acc[j][0]);
                acc[j][1] = fma2(xv23.x, wv2.y, acc[j][1]);
                acc[j][0] = fma2(xv23.y, wv3.x, acc[j][0]);
                acc[j][1] = fma2(xv23.y, wv3.y, acc[j][1]);
            }
        }

        // ---- prefetch own x region for t+1 (warp-private; own reads done above;
        //      LDG latency hides under the h-patch below)
        if (t + 1 < TT) {
            const float4* xsrc =
                (const float4*)(x + ((size_t)(b * TT + t + 1) * SS + 2 * p0) * CC);
            int i0 = pl * 4 + f * 2;
            #pragma unroll
            for (int q = 0; q < 2; q++) {
                float4 v = xsrc[i0 + q];
                xsD[(i0 + q) * 4 + 0] = dup2(v.x);
                xsD[(i0 + q) * 4 + 1] = dup2(v.y);
                xsD[(i0 + q) * 4 + 2] = dup2(v.z);
                xsD[(i0 + q) * 4 + 3] = dup2(v.w);
            }
        }

        // ---- h-patch: row-major merged k0/k1 taps. Row m feeds slot m (k0)
        // and slot m-1 (k1). Last warp's top row is the halo row (256).
        const int lastrow = (w == NWARPS - 1) ? 256 : (pl + NP);
        #pragma unroll
        for (int fg = 0; fg < FF / 2; fg++) {
            ulonglong2 w0a = *(const ulonglong2*)&w4s[(16 + fg * 2 + 0) * FF + f];
            ulonglong2 w0b = *(const ulonglong2*)&w4s[(16 + fg * 2 + 1) * FF + f];
            ulonglong2 w1a = *(const ulonglong2*)&w4s[(16 + FF + fg * 2 + 0) * FF + f];
            ulonglong2 w1b = *(const ulonglong2*)&w4s[(16 + FF + fg * 2 + 1) * FF + f];
            #pragma unroll
            for (int m = 0; m <= NP; m++) {
                const int row = (m == NP) ? lastrow : (pl + m);
                ulonglong2 hv = *(const ulonglong2*)&hrd[row * FF + fg * 2];
                if (m < NP) {
                    acc[m][0] = fma2(hv.x, w0a.x, acc[m][0]);
                    acc[m][1] = fma2(hv.x, w0a.y, acc[m][1]);
                    acc[m][0] = fma2(hv.y, w0b.x, acc[m][0]);
                    acc[m][1] = fma2(hv.y, w0b.y, acc[m][1]);
                }
                if (m > 0) {
                    acc[m - 1][0] = fma2(hv.x, w1a.x, acc[m - 1][0]);
                    acc[m - 1][1] = fma2(hv.x, w1a.y, acc[m - 1][1]);
                    acc[m - 1][0] = fma2(hv.y, w1b.x, acc[m - 1][0]);
                    acc[m - 1][1] = fma2(hv.y, w1b.y, acc[m - 1][1]);
                }
            }
        }

        // ---- cell update (c in regs), write OTHER parity buffer; halo push
        #pragma unroll
        for (int j = 0; j < NP; j++) {
            float2 a01 = unpack2(acc[j][0]);   // (zi, zf)
            float2 a23 = unpack2(acc[j][1]);   // (zc, zo)
            float i_g = hsig(a01.x);
            float f_g = hsig(a01.y);
            float cn = f_g * creg[j] + i_g * ftanh(a23.x);
            float hn = hsig(a23.y) * ftanh(cn);
            creg[j] = cn;
            ull hd = dup2(hn);
            hwr[(pl + j) * FF + f] = hd;
            if (j == 0 && w == 0 && rank > 0) {
                // left neighbor reads this in its (par^1) buffer halo row
                unsigned la = smem_u32(&hwr[256 * FF + f]);
                unsigned ra;
                asm("mapa.shared::cluster.u32 %0, %1, %2;"
                    : "=r"(ra) : "r"(la), "r"(rank - 1));
                asm volatile("st.shared::cluster.u64 [%0], %1;"
                             :: "r"(ra), "l"(hd) : "memory");
            }
        }

        // single cluster-wide barrier: orders local h writes, warp-private x,
        // and the remote halo push for the next step
        asm volatile("barrier.cluster.arrive.aligned;" ::: "memory");
        asm volatile("barrier.cluster.wait.aligned;" ::: "memory");
    }

    // ---- fused Dense(1): final h is in parity buffer 0 (TT even)
    {
        const ull* hfin = hsD;   // parity 0
        float partial = 0.0f;
        #pragma unroll
        for (int j = 0; j < NP; j++) {
            const int m = pl + j;
            partial += unpack2(hfin[m * FF + f]).x * dw[(p0 + m) * FF + f];
        }
        #pragma unroll
        for (int off = 16; off > 0; off >>= 1)
            partial += __shfl_down_sync(0xffffffffu, partial, off);
        float* red = (float*)xsD;   // reuse x scratch (all compute done)
        if (f == 0) red[w] = partial;
        __syncthreads();
        if (w == 0) {
            float s = (f < NWARPS) ? red[f] : 0.0f;
            #pragma unroll
            for (int off = 8; off > 0; off >>= 1)
                s += __shfl_down_sync(0xffffffffu, s, off);
            if (f == 0) atomicAdd(out + b, s);
        }
    }
}

extern "C" void kernel_launch(void* const* d_in, const int* in_sizes, int n_in,
                              void* d_out, int out_size) {
    const float* x    = (const float*)d_in[0];  // (32,50,2048,8)
    const float* kern = (const float*)d_in[1];  // (2,8,128)
    const float* rk   = (const float*)d_in[2];  // (2,32,128)
    const float* bias = (const float*)d_in[3];  // (128,)
    const float* dw   = (const float*)d_in[4];  // (32768,1)
    const float* db   = (const float*)d_in[5];  // (1,)
    float* out = (float*)d_out;                  // (32,1)

    const int smem_bytes = RDIM * FF * 16 + XS_N * 8 + 2 * HBUF * 8; // 205312
    static int configured = 0;
    if (!configured) {
        cudaFuncSetAttribute(lstm_kernel, cudaFuncAttributeMaxDynamicSharedMemorySize,
                             smem_bytes);
        configured = 1;
    }

    init_out_kernel<<<1, 32>>>(db, out);
    dim3 grid(CLUSTER_X, BB);   // 128 CTAs = 32 clusters of 4 (one batch each)
    lstm_kernel<<<grid, NTHREADS, smem_bytes>>>(x, kern, rk, bias, dw, out);
}